// round 2
// baseline (speedup 1.0000x reference)
#include <cuda_runtime.h>
#include <math.h>

// ---------------- device scratch (static, no allocation) ----------------
__device__ float g_xiou[2048 * 2304];   // tree_features @ W_iou^T + b_iou
__device__ float g_xf  [2048 * 768];    // tree_features @ W_f^T + b_f
__device__ float g_xih [2048 * 3072];   // features @ W_ih^T + b_ih + b_hh
__device__ float g_h   [2048 * 768];    // tree h
__device__ float g_c   [2048 * 768];    // tree c
__device__ float g_hsum[512  * 768];    // compact child-h sums per level
__device__ float g_iou [512  * 2304];   // hsum @ U_iou^T per level
__device__ float g_fh  [1024 * 768];    // child_h @ U_f^T per level
__device__ float g_hall[2048 * 768];    // seq-LSTM h history
__device__ float g_hbuf[2 * 768];       // seq-LSTM h double buffer
__device__ float g_cls [2048 * 1536];   // concat(tree_h, lstm_h)
__device__ float g_logits[2048 * 128];
__device__ unsigned g_ctr;              // step arrive counter (self-resetting)
__device__ unsigned g_done;             // departure counter (self-resetting)

__device__ __forceinline__ float sigf(float x) { return 1.0f / (1.0f + expf(-x)); }

// ---------------- generic fp32 GEMM: C[M,N] = A[M,K] @ B[N,K]^T + b1 + b2 ----
// Requires N % 128 == 0, K % 8 == 0. M arbitrary (guarded).
__global__ void __launch_bounds__(256, 1) sgemm_nt(
    const float* __restrict__ A, const float* __restrict__ B,
    const float* __restrict__ b1, const float* __restrict__ b2,
    float* __restrict__ C, int M, int N, int K)
{
    __shared__ float As[8][128];
    __shared__ float Bs[8][128];
    const int bm = blockIdx.y * 128;
    const int bn = blockIdx.x * 128;
    const int tid = threadIdx.x;
    const int lr = tid >> 1;          // 0..127 row within tile
    const int lc = (tid & 1) * 4;     // 0 or 4 within BK=8
    const int tx = tid & 15;          // n micro-tile
    const int ty = tid >> 4;          // m micro-tile

    float acc[8][8];
#pragma unroll
    for (int i = 0; i < 8; i++)
#pragma unroll
        for (int j = 0; j < 8; j++) acc[i][j] = 0.0f;

    const bool aval = (bm + lr) < M;
    const float* Aptr = A + (size_t)(bm + lr) * K + lc;
    const float* Bptr = B + (size_t)(bn + lr) * K + lc;

    for (int k0 = 0; k0 < K; k0 += 8) {
        float4 av = aval ? *(const float4*)(Aptr + k0) : make_float4(0.f, 0.f, 0.f, 0.f);
        float4 bv = *(const float4*)(Bptr + k0);
        As[lc + 0][lr] = av.x; As[lc + 1][lr] = av.y;
        As[lc + 2][lr] = av.z; As[lc + 3][lr] = av.w;
        Bs[lc + 0][lr] = bv.x; Bs[lc + 1][lr] = bv.y;
        Bs[lc + 2][lr] = bv.z; Bs[lc + 3][lr] = bv.w;
        __syncthreads();
#pragma unroll
        for (int kk = 0; kk < 8; kk++) {
            float ra[8], rb[8];
#pragma unroll
            for (int i = 0; i < 8; i++) ra[i] = As[kk][ty * 8 + i];
#pragma unroll
            for (int j = 0; j < 8; j++) rb[j] = Bs[kk][tx * 8 + j];
#pragma unroll
            for (int i = 0; i < 8; i++)
#pragma unroll
                for (int j = 0; j < 8; j++) acc[i][j] = fmaf(ra[i], rb[j], acc[i][j]);
        }
        __syncthreads();
    }

#pragma unroll
    for (int i = 0; i < 8; i++) {
        int row = bm + ty * 8 + i;
        if (row < M) {
#pragma unroll
            for (int j = 0; j < 8; j++) {
                int col = bn + tx * 8 + j;
                float v = acc[i][j];
                if (b1) v += b1[col];
                if (b2) v += b2[col];
                C[(size_t)row * N + col] = v;
            }
        }
    }
}

// ---------------- tree LSTM elementwise kernels ----------------
__global__ void leaf_combine() {
    int idx = blockIdx.x * blockDim.x + threadIdx.x;   // 1024*768 exact
    int p = 1024 + idx / 768, jj = idx % 768;
    const float* xr = g_xiou + (size_t)p * 2304;
    float i = sigf(xr[jj]);
    float o = sigf(xr[768 + jj]);
    float u = tanhf(xr[1536 + jj]);
    float cn = i * u;
    g_c[(size_t)p * 768 + jj] = cn;
    g_h[(size_t)p * 768 + jj] = o * tanhf(cn);
}

__global__ void gather_hsum(int s, int cnt) {
    int idx = blockIdx.x * blockDim.x + threadIdx.x;
    if (idx >= cnt * 768) return;
    int r = idx / 768, jj = idx % 768, p = s + r;
    int c0 = 2 * p + 1, c1 = 2 * p + 2;
    float v = g_h[(size_t)c0 * 768 + jj];
    if (c1 < 2048) v += g_h[(size_t)c1 * 768 + jj];
    g_hsum[idx] = v;
}

__global__ void node_combine(int s, int cnt, int cs) {
    int idx = blockIdx.x * blockDim.x + threadIdx.x;
    if (idx >= cnt * 768) return;
    int r = idx / 768, jj = idx % 768, p = s + r;
    const float* xr = g_xiou + (size_t)p * 2304;
    const float* ir = g_iou + (size_t)r * 2304;
    float i = sigf(xr[jj] + ir[jj]);
    float o = sigf(xr[768 + jj] + ir[768 + jj]);
    float u = tanhf(xr[1536 + jj] + ir[1536 + jj]);
    float xfv = g_xf[(size_t)p * 768 + jj];
    int c0 = 2 * p + 1, c1 = 2 * p + 2;
    float fc = sigf(xfv + g_fh[(size_t)(c0 - cs) * 768 + jj]) * g_c[(size_t)c0 * 768 + jj];
    if (c1 < 2048)
        fc += sigf(xfv + g_fh[(size_t)(c1 - cs) * 768 + jj]) * g_c[(size_t)c1 * 768 + jj];
    float cn = i * u + fc;
    g_c[(size_t)p * 768 + jj] = cn;
    g_h[(size_t)p * 768 + jj] = o * tanhf(cn);
}

// ---------------- sequential LSTM: persistent, W_hh in registers ----------
// 96 CTAs x 256 threads. Warp w of CTA b owns output j = b*8+w.
// Lane l holds W_hh[{j,768+j,1536+j,2304+j}][l*4 + 128*i + c], i<6, c<4 (96 regs).
__global__ void __launch_bounds__(256, 1) lstm_seq(const float* __restrict__ Whh) {
    const int w = threadIdx.x >> 5;
    const int l = threadIdx.x & 31;
    const int j = blockIdx.x * 8 + w;
    const unsigned G = gridDim.x;

    float wr[4][24];
#pragma unroll
    for (int g = 0; g < 4; g++) {
        const float* base = Whh + (size_t)(g * 768 + j) * 768;
#pragma unroll
        for (int i = 0; i < 6; i++) {
            float4 v = *(const float4*)(base + 128 * i + l * 4);
            wr[g][i * 4 + 0] = v.x; wr[g][i * 4 + 1] = v.y;
            wr[g][i * 4 + 2] = v.z; wr[g][i * 4 + 3] = v.w;
        }
    }

    float cprev = 0.0f;
    for (int t = 0; t < 2048; t++) {
        // independent of h -> issue early
        float xi = g_xih[(size_t)t * 3072 + j];
        float xf = g_xih[(size_t)t * 3072 + 768 + j];
        float xg = g_xih[(size_t)t * 3072 + 1536 + j];
        float xo = g_xih[(size_t)t * 3072 + 2304 + j];

        const float4* hp = (const float4*)(g_hbuf + (t & 1) * 768);
        float a0 = 0.f, a1 = 0.f, a2 = 0.f, a3 = 0.f;
#pragma unroll
        for (int i = 0; i < 6; i++) {
            float4 hv = __ldcg(hp + i * 32 + l);   // L2-coherent read
            a0 = fmaf(wr[0][i * 4 + 0], hv.x, a0); a0 = fmaf(wr[0][i * 4 + 1], hv.y, a0);
            a0 = fmaf(wr[0][i * 4 + 2], hv.z, a0); a0 = fmaf(wr[0][i * 4 + 3], hv.w, a0);
            a1 = fmaf(wr[1][i * 4 + 0], hv.x, a1); a1 = fmaf(wr[1][i * 4 + 1], hv.y, a1);
            a1 = fmaf(wr[1][i * 4 + 2], hv.z, a1); a1 = fmaf(wr[1][i * 4 + 3], hv.w, a1);
            a2 = fmaf(wr[2][i * 4 + 0], hv.x, a2); a2 = fmaf(wr[2][i * 4 + 1], hv.y, a2);
            a2 = fmaf(wr[2][i * 4 + 2], hv.z, a2); a2 = fmaf(wr[2][i * 4 + 3], hv.w, a2);
            a3 = fmaf(wr[3][i * 4 + 0], hv.x, a3); a3 = fmaf(wr[3][i * 4 + 1], hv.y, a3);
            a3 = fmaf(wr[3][i * 4 + 2], hv.z, a3); a3 = fmaf(wr[3][i * 4 + 3], hv.w, a3);
        }
#pragma unroll
        for (int off = 16; off > 0; off >>= 1) {
            a0 += __shfl_xor_sync(0xffffffffu, a0, off);
            a1 += __shfl_xor_sync(0xffffffffu, a1, off);
            a2 += __shfl_xor_sync(0xffffffffu, a2, off);
            a3 += __shfl_xor_sync(0xffffffffu, a3, off);
        }
        if (l == 0) {
            float iv = sigf(a0 + xi);
            float fv = sigf(a1 + xf);
            float gv = tanhf(a2 + xg);
            float ov = sigf(a3 + xo);
            float cn = fv * cprev + iv * gv;
            cprev = cn;
            float hn = ov * tanhf(cn);
            g_hall[(size_t)t * 768 + j] = hn;
            g_hbuf[((t + 1) & 1) * 768 + j] = hn;
            __threadfence();
        }
        __syncthreads();
        if (threadIdx.x == 0) {
            atomicAdd(&g_ctr, 1u);
            unsigned target = G * (unsigned)(t + 1);
            while (*((volatile unsigned*)&g_ctr) < target) {}
            __threadfence();
        }
        __syncthreads();
    }

    // graph-replay-safe reset: departure round so nobody is still spinning on g_ctr
    __syncthreads();
    if (threadIdx.x == 0) {
        __threadfence();
        atomicAdd(&g_done, 1u);
        if (blockIdx.x == 0) {
            while (*((volatile unsigned*)&g_done) < G) {}
            g_ctr = 0u;
            __threadfence();
            g_done = 0u;
            __threadfence();
        }
    }
}

// ---------------- misc ----------------
__global__ void zero_hbuf() {
    int i = blockIdx.x * blockDim.x + threadIdx.x;
    if (i < 1536) g_hbuf[i] = 0.0f;
}

__global__ void concat_cls() {
    int idx = blockIdx.x * blockDim.x + threadIdx.x;   // 2048*1536 exact
    int t = idx / 1536, k = idx % 1536;
    g_cls[idx] = (k < 768) ? g_h[(size_t)t * 768 + k]
                           : g_hall[(size_t)t * 768 + (k - 768)];
}

__global__ void logsoftmax_col(float* __restrict__ out) {
    int o = blockIdx.x;            // 128 columns
    int tid = threadIdx.x;         // 256 threads
    __shared__ float red[256];
    float m = -1e30f;
    for (int t = tid; t < 2048; t += 256) m = fmaxf(m, g_logits[(size_t)t * 128 + o]);
    red[tid] = m; __syncthreads();
    for (int st = 128; st > 0; st >>= 1) {
        if (tid < st) red[tid] = fmaxf(red[tid], red[tid + st]);
        __syncthreads();
    }
    m = red[0]; __syncthreads();
    float s = 0.0f;
    for (int t = tid; t < 2048; t += 256) s += expf(g_logits[(size_t)t * 128 + o] - m);
    red[tid] = s; __syncthreads();
    for (int st = 128; st > 0; st >>= 1) {
        if (tid < st) red[tid] += red[tid + st];
        __syncthreads();
    }
    float lse = m + logf(red[0]);
    for (int t = tid; t < 2048; t += 256)
        out[(size_t)t * 128 + o] = g_logits[(size_t)t * 128 + o] - lse;
}

// ---------------- host ----------------
extern "C" void kernel_launch(void* const* d_in, const int* in_sizes, int n_in,
                              void* d_out, int out_size)
{
    const float* tree_features = (const float*)d_in[0];
    const float* features      = (const float*)d_in[1];
    const float* W_iou = (const float*)d_in[2];
    const float* b_iou = (const float*)d_in[3];
    const float* U_iou = (const float*)d_in[4];
    const float* W_f   = (const float*)d_in[5];
    const float* b_f   = (const float*)d_in[6];
    const float* U_f   = (const float*)d_in[7];
    const float* W_ih  = (const float*)d_in[8];
    const float* b_ih  = (const float*)d_in[9];
    const float* W_hh  = (const float*)d_in[10];
    const float* b_hh  = (const float*)d_in[11];
    const float* W_cls = (const float*)d_in[12];
    const float* b_cls = (const float*)d_in[13];
    float* out = (float*)d_out;

    float *xiou, *xf, *xih, *h, *hsum, *iou, *fh, *cls, *logits;
    cudaGetSymbolAddress((void**)&xiou,   g_xiou);
    cudaGetSymbolAddress((void**)&xf,     g_xf);
    cudaGetSymbolAddress((void**)&xih,    g_xih);
    cudaGetSymbolAddress((void**)&h,      g_h);
    cudaGetSymbolAddress((void**)&hsum,   g_hsum);
    cudaGetSymbolAddress((void**)&iou,    g_iou);
    cudaGetSymbolAddress((void**)&fh,     g_fh);
    cudaGetSymbolAddress((void**)&cls,    g_cls);
    cudaGetSymbolAddress((void**)&logits, g_logits);

    auto gemm = [](const float* A, const float* B, const float* bb1, const float* bb2,
                   float* C, int M, int N, int K) {
        dim3 grid(N / 128, (M + 127) / 128);
        sgemm_nt<<<grid, 256>>>(A, B, bb1, bb2, C, M, N, K);
    };

    // precompute input projections
    gemm(tree_features, W_iou, b_iou, nullptr, xiou, 2048, 2304, 768);
    gemm(tree_features, W_f,   b_f,   nullptr, xf,   2048, 768,  768);
    gemm(features,      W_ih,  b_ih,  b_hh,    xih,  2048, 3072, 768);
    zero_hbuf<<<6, 256>>>();

    // tree LSTM, level by level (levels are contiguous index ranges)
    leaf_combine<<<(1024 * 768) / 256, 256>>>();
    for (int lvl = 1; lvl <= 11; lvl++) {
        int s, cnt, cs, e;
        if (lvl <= 10) {
            s = 1 << (10 - lvl);
            cnt = s;
            cs = 2 * s + 1;
            int last = 4 * s; if (last > 2047) last = 2047;
            e = last - 2 * s;
        } else {
            s = 0; cnt = 1; cs = 1; e = 2;
        }
        gather_hsum<<<(cnt * 768 + 255) / 256, 256>>>(s, cnt);
        gemm(hsum, U_iou, nullptr, nullptr, iou, cnt, 2304, 768);
        gemm(h + (size_t)cs * 768, U_f, nullptr, nullptr, fh, e, 768, 768);
        node_combine<<<(cnt * 768 + 255) / 256, 256>>>(s, cnt, cs);
    }

    // sequential LSTM (persistent, register-resident W_hh)
    lstm_seq<<<96, 256>>>(W_hh);

    // classifier + log_softmax over axis 0
    concat_cls<<<(2048 * 1536) / 256, 256>>>();
    gemm(cls, W_cls, b_cls, nullptr, logits, 2048, 128, 1536);
    logsoftmax_col<<<128, 256>>>(out);
}

// round 3
// speedup vs baseline: 1.4523x; 1.4523x over previous
#include <cuda_runtime.h>
#include <math.h>

// ---------------- device scratch (static, no allocation) ----------------
__device__ float g_xiou[2048 * 2304];   // tree_features @ W_iou^T + b_iou
__device__ float g_xf  [2048 * 768];    // tree_features @ W_f^T + b_f
__device__ float g_xih [2048 * 3072];   // features @ W_ih^T + b_ih + b_hh
__device__ float g_h   [2048 * 768];    // tree h
__device__ float g_c   [2048 * 768];    // tree c
__device__ float g_iou [512  * 2304];   // (child-h-sum) @ U_iou^T per level
__device__ float g_fh  [1024 * 768];    // child_h @ U_f^T per level
__device__ float g_hbuf[2 * 768];       // seq-LSTM h double buffer
__device__ float g_cls [2048 * 1536];   // concat(tree_h, lstm_h) written in place
__device__ float g_logits[2048 * 128];
__device__ unsigned g_ctr;              // step arrive counter (self-resetting)
__device__ unsigned g_done;             // departure counter (self-resetting)

// ---------------- helpers ----------------
__device__ __forceinline__ unsigned long long pk2(float x, float y) {
    unsigned long long d;
    asm("mov.b64 %0, {%1, %2};" : "=l"(d) : "f"(x), "f"(y));
    return d;
}
__device__ __forceinline__ void upk2(unsigned long long d, float& x, float& y) {
    asm("mov.b64 {%0, %1}, %2;" : "=f"(x), "=f"(y) : "l"(d));
}
__device__ __forceinline__ void fma2(unsigned long long& c, unsigned long long a,
                                     unsigned long long b) {
    asm("fma.rn.f32x2 %0, %1, %2, %0;" : "+l"(c) : "l"(a), "l"(b));
}
__device__ __forceinline__ unsigned ld_acq(const unsigned* p) {
    unsigned v;
    asm volatile("ld.acquire.gpu.u32 %0, [%1];" : "=r"(v) : "l"(p));
    return v;
}
__device__ __forceinline__ void red_rel(unsigned* p, unsigned v) {
    asm volatile("red.release.gpu.add.u32 [%0], %1;" :: "l"(p), "r"(v));
}
__device__ __forceinline__ float fsig(float x) {
    return __fdividef(1.0f, 1.0f + __expf(-x));
}
__device__ __forceinline__ float ftanh(float x) {
    float xx = fminf(fmaxf(x, -15.0f), 15.0f);
    float e = __expf(2.0f * xx);
    return __fdividef(e - 1.0f, e + 1.0f);
}

// ---------------- 64x64 tile GEMM, f32x2-packed FFMA ----------------
// C[M,N] = A[M,K] @ B[N,K]^T (+b1 +b2). N%64==0, K%16==0, M guarded.
// hs >= 0: A row r is g_h[2*(hs+r)+1] + g_h[2*(hs+r)+2] (tree child-h sum).
struct GemmP {
    const float* A; const float* B; const float* b1; const float* b2;
    float* C; int M, N, K, hs;
};

__device__ __forceinline__ void gemm_tile(const GemmP p, int tile) {
    __shared__ __align__(16) float As[16][68];
    __shared__ __align__(16) float Bs[16][68];
    const int ntx = p.N >> 6;
    const int bm = (tile / ntx) * 64;
    const int bn = (tile % ntx) * 64;
    const int tid = threadIdx.x;
    const int lr = tid >> 2;
    const int lc = (tid & 3) * 4;
    const int ty = tid >> 4;
    const int tx = tid & 15;

    unsigned long long acc[4][2];
#pragma unroll
    for (int i = 0; i < 4; i++) { acc[i][0] = 0ull; acc[i][1] = 0ull; }

    const int gr = bm + lr;
    const bool av = gr < p.M;
    const float* Brow = p.B + (size_t)(bn + lr) * p.K + lc;
    const float* Arow;
    const float* Arow2 = nullptr;
    bool has2 = false;
    if (p.hs >= 0) {
        int pp = p.hs + (av ? gr : 0);
        Arow  = g_h + (size_t)(2 * pp + 1) * 768 + lc;
        has2  = (2 * pp + 2) < 2048;
        Arow2 = g_h + (size_t)(2 * pp + 2) * 768 + lc;
    } else {
        Arow = p.A + (size_t)(av ? gr : 0) * p.K + lc;
    }

    for (int k0 = 0; k0 < p.K; k0 += 16) {
        float4 a = make_float4(0.f, 0.f, 0.f, 0.f);
        if (av) {
            a = *(const float4*)(Arow + k0);
            if (p.hs >= 0 && has2) {
                float4 a2 = *(const float4*)(Arow2 + k0);
                a.x += a2.x; a.y += a2.y; a.z += a2.z; a.w += a2.w;
            }
        }
        float4 b = *(const float4*)(Brow + k0);
        __syncthreads();
        As[lc + 0][lr] = a.x; As[lc + 1][lr] = a.y;
        As[lc + 2][lr] = a.z; As[lc + 3][lr] = a.w;
        Bs[lc + 0][lr] = b.x; Bs[lc + 1][lr] = b.y;
        Bs[lc + 2][lr] = b.z; Bs[lc + 3][lr] = b.w;
        __syncthreads();
#pragma unroll
        for (int kk = 0; kk < 16; kk++) {
            float4 ra = *(const float4*)&As[kk][ty * 4];
            float4 rb = *(const float4*)&Bs[kk][tx * 4];
            unsigned long long b01 = pk2(rb.x, rb.y);
            unsigned long long b23 = pk2(rb.z, rb.w);
            unsigned long long aa;
            aa = pk2(ra.x, ra.x); fma2(acc[0][0], aa, b01); fma2(acc[0][1], aa, b23);
            aa = pk2(ra.y, ra.y); fma2(acc[1][0], aa, b01); fma2(acc[1][1], aa, b23);
            aa = pk2(ra.z, ra.z); fma2(acc[2][0], aa, b01); fma2(acc[2][1], aa, b23);
            aa = pk2(ra.w, ra.w); fma2(acc[3][0], aa, b01); fma2(acc[3][1], aa, b23);
        }
    }

#pragma unroll
    for (int i = 0; i < 4; i++) {
        int row = bm + ty * 4 + i;
        if (row < p.M) {
            float4 o;
            upk2(acc[i][0], o.x, o.y);
            upk2(acc[i][1], o.z, o.w);
            int col = bn + tx * 4;
            if (p.b1) {
                float4 bb = *(const float4*)(p.b1 + col);
                o.x += bb.x; o.y += bb.y; o.z += bb.z; o.w += bb.w;
            }
            if (p.b2) {
                float4 bb = *(const float4*)(p.b2 + col);
                o.x += bb.x; o.y += bb.y; o.z += bb.z; o.w += bb.w;
            }
            *(float4*)(p.C + (size_t)row * p.N + col) = o;
        }
    }
}

__global__ void __launch_bounds__(256) gemm_single(GemmP p) {
    gemm_tile(p, blockIdx.x);
}

__global__ void __launch_bounds__(256) gemm_dual(GemmP p1, GemmP p2, int t1) {
    int b = blockIdx.x;
    GemmP p = (b < t1) ? p1 : p2;
    int tile = (b < t1) ? b : b - t1;
    gemm_tile(p, tile);
}

// ---------------- tree LSTM elementwise kernels ----------------
__global__ void leaf_combine() {
    int idx = blockIdx.x * blockDim.x + threadIdx.x;   // 1024*768 exact
    int p = 1024 + idx / 768, jj = idx % 768;
    const float* xr = g_xiou + (size_t)p * 2304;
    float i = fsig(xr[jj]);
    float o = fsig(xr[768 + jj]);
    float u = ftanh(xr[1536 + jj]);
    float cn = i * u;
    float hn = o * ftanh(cn);
    g_c[(size_t)p * 768 + jj] = cn;
    g_h[(size_t)p * 768 + jj] = hn;
    g_cls[(size_t)p * 1536 + jj] = hn;
}

__global__ void node_combine(int s, int cnt, int cs) {
    int idx = blockIdx.x * blockDim.x + threadIdx.x;
    if (idx >= cnt * 768) return;
    int r = idx / 768, jj = idx % 768, p = s + r;
    const float* xr = g_xiou + (size_t)p * 2304;
    const float* ir = g_iou + (size_t)r * 2304;
    float i = fsig(xr[jj] + ir[jj]);
    float o = fsig(xr[768 + jj] + ir[768 + jj]);
    float u = ftanh(xr[1536 + jj] + ir[1536 + jj]);
    float xfv = g_xf[(size_t)p * 768 + jj];
    int c0 = 2 * p + 1, c1 = 2 * p + 2;
    float fc = fsig(xfv + g_fh[(size_t)(c0 - cs) * 768 + jj]) * g_c[(size_t)c0 * 768 + jj];
    if (c1 < 2048)
        fc += fsig(xfv + g_fh[(size_t)(c1 - cs) * 768 + jj]) * g_c[(size_t)c1 * 768 + jj];
    float cn = i * u + fc;
    float hn = o * ftanh(cn);
    g_c[(size_t)p * 768 + jj] = cn;
    g_h[(size_t)p * 768 + jj] = hn;
    g_cls[(size_t)p * 1536 + jj] = hn;
}

// ---------------- sequential LSTM: persistent, W_hh in registers ----------
// 96 CTAs x 256 threads. Warp w of CTA b owns output j = b*8+w.
// Lane l holds W_hh[{j,768+j,1536+j,2304+j}][l*4 + 128*i + c], packed f32x2.
__global__ void __launch_bounds__(256) lstm_seq(const float* __restrict__ Whh) {
    const int w = threadIdx.x >> 5;
    const int l = threadIdx.x & 31;
    const int j = blockIdx.x * 8 + w;
    const unsigned G = gridDim.x;

    unsigned long long wr2[4][12];
#pragma unroll
    for (int g = 0; g < 4; g++) {
        const float* base = Whh + (size_t)(g * 768 + j) * 768;
#pragma unroll
        for (int i = 0; i < 6; i++) {
            float4 v = *(const float4*)(base + 128 * i + l * 4);
            wr2[g][2 * i]     = pk2(v.x, v.y);
            wr2[g][2 * i + 1] = pk2(v.z, v.w);
        }
    }

    float cprev = 0.0f;
    // prefetch x gates for t=0
    float xi = g_xih[j], xf_ = g_xih[768 + j], xg = g_xih[1536 + j], xo = g_xih[2304 + j];

    for (int t = 0; t < 2048; t++) {
        const float4* hp = (const float4*)(g_hbuf + (t & 1) * 768);
        unsigned long long A0 = 0ull, A1 = 0ull, A2 = 0ull, A3 = 0ull;
#pragma unroll
        for (int i = 0; i < 6; i++) {
            float4 hv = __ldcg(hp + i * 32 + l);
            unsigned long long h01 = pk2(hv.x, hv.y);
            unsigned long long h23 = pk2(hv.z, hv.w);
            fma2(A0, wr2[0][2 * i], h01); fma2(A0, wr2[0][2 * i + 1], h23);
            fma2(A1, wr2[1][2 * i], h01); fma2(A1, wr2[1][2 * i + 1], h23);
            fma2(A2, wr2[2][2 * i], h01); fma2(A2, wr2[2][2 * i + 1], h23);
            fma2(A3, wr2[3][2 * i], h01); fma2(A3, wr2[3][2 * i + 1], h23);
        }
        float a0, a1, a2, a3, tlo, thi;
        upk2(A0, tlo, thi); a0 = tlo + thi;
        upk2(A1, tlo, thi); a1 = tlo + thi;
        upk2(A2, tlo, thi); a2 = tlo + thi;
        upk2(A3, tlo, thi); a3 = tlo + thi;
#pragma unroll
        for (int off = 16; off > 0; off >>= 1) {
            a0 += __shfl_xor_sync(0xffffffffu, a0, off);
            a1 += __shfl_xor_sync(0xffffffffu, a1, off);
            a2 += __shfl_xor_sync(0xffffffffu, a2, off);
            a3 += __shfl_xor_sync(0xffffffffu, a3, off);
        }
        if (l == 0) {
            float iv = fsig(a0 + xi);
            float fv = fsig(a1 + xf_);
            float gv = ftanh(a2 + xg);
            float ov = fsig(a3 + xo);
            float cn = fv * cprev + iv * gv;
            cprev = cn;
            float hn = ov * ftanh(cn);
            __stcg(&g_cls[(size_t)t * 1536 + 768 + j], hn);
            __stcg(&g_hbuf[((t + 1) & 1) * 768 + j], hn);
        }
        __syncthreads();
        if (threadIdx.x == 0) red_rel(&g_ctr, 1u);

        // prefetch next step's x gates during the wait window
        float nxi = 0.f, nxf = 0.f, nxg = 0.f, nxo = 0.f;
        if (t + 1 < 2048) {
            const float* xb = g_xih + (size_t)(t + 1) * 3072 + j;
            nxi = xb[0]; nxf = xb[768]; nxg = xb[1536]; nxo = xb[2304];
        }
        if (l == 0) {
            unsigned tgt = G * (unsigned)(t + 1);
            while (ld_acq(&g_ctr) < tgt) {}
        }
        __syncwarp();
        xi = nxi; xf_ = nxf; xg = nxg; xo = nxo;
    }

    // graph-replay-safe reset: departure round so nobody still spins on g_ctr
    __syncthreads();
    if (threadIdx.x == 0) {
        red_rel(&g_done, 1u);
        if (blockIdx.x == 0) {
            while (ld_acq(&g_done) < G) {}
            *((volatile unsigned*)&g_ctr) = 0u;
            __threadfence();
            *((volatile unsigned*)&g_done) = 0u;
            __threadfence();
        }
    }
}

// ---------------- misc ----------------
__global__ void zero_hbuf() {
    int i = blockIdx.x * blockDim.x + threadIdx.x;
    if (i < 1536) g_hbuf[i] = 0.0f;
}

__global__ void logsoftmax_col(float* __restrict__ out) {
    int o = blockIdx.x;            // 128 columns
    int tid = threadIdx.x;         // 256 threads
    __shared__ float red[256];
    float m = -1e30f;
    for (int t = tid; t < 2048; t += 256) m = fmaxf(m, g_logits[(size_t)t * 128 + o]);
    red[tid] = m; __syncthreads();
    for (int st = 128; st > 0; st >>= 1) {
        if (tid < st) red[tid] = fmaxf(red[tid], red[tid + st]);
        __syncthreads();
    }
    m = red[0]; __syncthreads();
    float s = 0.0f;
    for (int t = tid; t < 2048; t += 256) s += expf(g_logits[(size_t)t * 128 + o] - m);
    red[tid] = s; __syncthreads();
    for (int st = 128; st > 0; st >>= 1) {
        if (tid < st) red[tid] += red[tid + st];
        __syncthreads();
    }
    float lse = m + logf(red[0]);
    for (int t = tid; t < 2048; t += 256)
        out[(size_t)t * 128 + o] = g_logits[(size_t)t * 128 + o] - lse;
}

// ---------------- host ----------------
static inline int ntiles(int M, int N) { return ((M + 63) / 64) * (N / 64); }

extern "C" void kernel_launch(void* const* d_in, const int* in_sizes, int n_in,
                              void* d_out, int out_size)
{
    const float* tree_features = (const float*)d_in[0];
    const float* features      = (const float*)d_in[1];
    const float* W_iou = (const float*)d_in[2];
    const float* b_iou = (const float*)d_in[3];
    const float* U_iou = (const float*)d_in[4];
    const float* W_f   = (const float*)d_in[5];
    const float* b_f   = (const float*)d_in[6];
    const float* U_f   = (const float*)d_in[7];
    const float* W_ih  = (const float*)d_in[8];
    const float* b_ih  = (const float*)d_in[9];
    const float* W_hh  = (const float*)d_in[10];
    const float* b_hh  = (const float*)d_in[11];
    const float* W_cls = (const float*)d_in[12];
    const float* b_cls = (const float*)d_in[13];
    float* out = (float*)d_out;

    float *xiou, *xf, *xih, *h, *iou, *fh, *cls, *logits;
    cudaGetSymbolAddress((void**)&xiou,   g_xiou);
    cudaGetSymbolAddress((void**)&xf,     g_xf);
    cudaGetSymbolAddress((void**)&xih,    g_xih);
    cudaGetSymbolAddress((void**)&h,      g_h);
    cudaGetSymbolAddress((void**)&iou,    g_iou);
    cudaGetSymbolAddress((void**)&fh,     g_fh);
    cudaGetSymbolAddress((void**)&cls,    g_cls);
    cudaGetSymbolAddress((void**)&logits, g_logits);

    static cudaStream_t s2 = nullptr;
    static cudaEvent_t evFork = nullptr, evJoin = nullptr;
    if (!s2) {
        cudaStreamCreateWithFlags(&s2, cudaStreamNonBlocking);
        cudaEventCreateWithFlags(&evFork, cudaEventDisableTiming);
        cudaEventCreateWithFlags(&evJoin, cudaEventDisableTiming);
    }

    // ---- seq-LSTM branch prerequisites (stream 0) ----
    GemmP pih = { features, W_ih, b_ih, b_hh, xih, 2048, 3072, 768, -1 };
    gemm_single<<<ntiles(2048, 3072), 256>>>(pih);
    zero_hbuf<<<6, 256>>>();

    // ---- fork: seq LSTM on its own stream, overlapped with the tree ----
    cudaEventRecord(evFork, 0);
    cudaStreamWaitEvent(s2, evFork, 0);
    lstm_seq<<<96, 256, 0, s2>>>(W_hh);
    cudaEventRecord(evJoin, s2);

    // ---- tree branch (stream 0) ----
    GemmP piou = { tree_features, W_iou, b_iou, nullptr, xiou, 2048, 2304, 768, -1 };
    gemm_single<<<ntiles(2048, 2304), 256>>>(piou);
    GemmP pxf = { tree_features, W_f, b_f, nullptr, xf, 2048, 768, 768, -1 };
    gemm_single<<<ntiles(2048, 768), 256>>>(pxf);

    leaf_combine<<<(1024 * 768) / 256, 256>>>();
    for (int lvl = 1; lvl <= 11; lvl++) {
        int s, cnt, cs, e;
        if (lvl <= 10) {
            s = 1 << (10 - lvl);
            cnt = s;
            cs = 2 * s + 1;
            int last = 4 * s; if (last > 2047) last = 2047;
            e = last - 2 * s;
        } else {
            s = 0; cnt = 1; cs = 1; e = 2;
        }
        // task1: iou = hsum(children) @ U_iou^T  (A fused from g_h)
        GemmP p1 = { nullptr, U_iou, nullptr, nullptr, iou, cnt, 2304, 768, s };
        // task2: fh = child_h @ U_f^T
        GemmP p2 = { h + (size_t)cs * 768, U_f, nullptr, nullptr, fh, e, 768, 768, -1 };
        int t1 = ntiles(cnt, 2304), t2 = ntiles(e, 768);
        gemm_dual<<<t1 + t2, 256>>>(p1, p2, t1);
        node_combine<<<(cnt * 768 + 255) / 256, 256>>>(s, cnt, cs);
    }

    // ---- join + classifier + log_softmax over axis 0 ----
    cudaStreamWaitEvent(0, evJoin, 0);
    GemmP pcls = { cls, W_cls, b_cls, nullptr, logits, 2048, 128, 1536, -1 };
    gemm_single<<<ntiles(2048, 128), 256>>>(pcls);
    logsoftmax_col<<<128, 256>>>(out);
}

// round 5
// speedup vs baseline: 2.0789x; 1.4314x over previous
#include <cuda_runtime.h>
#include <math.h>

// ---------------- device scratch (static, no allocation) ----------------
__device__ float g_xiou[2048 * 2304];   // tree_features @ W_iou^T + b_iou
__device__ float g_xf  [2048 * 768];    // tree_features @ W_f^T + b_f
__device__ float g_xih [2048 * 3072];   // features @ W_ih^T + b_ih + b_hh
__device__ float g_h   [2048 * 768];    // tree h
__device__ float g_c   [2048 * 768];    // tree c
__device__ float g_iou [512  * 2304];   // (child-h-sum) @ U_iou^T per level
__device__ float g_fh  [1024 * 768];    // child_h @ U_f^T per level
__device__ float g_hbuf[2 * 768];       // seq-LSTM h double buffer
__device__ float g_cls [2048 * 1536];   // concat(tree_h, lstm_h) written in place
__device__ float g_logits[2048 * 128];
__device__ unsigned g_ctr;              // step arrive counter
__device__ unsigned g_done;             // departure counter

// ---------------- helpers ----------------
__device__ __forceinline__ unsigned long long pk2(float x, float y) {
    unsigned long long d;
    asm("mov.b64 %0, {%1, %2};" : "=l"(d) : "f"(x), "f"(y));
    return d;
}
__device__ __forceinline__ void upk2(unsigned long long d, float& x, float& y) {
    asm("mov.b64 {%0, %1}, %2;" : "=f"(x), "=f"(y) : "l"(d));
}
__device__ __forceinline__ void fma2(unsigned long long& c, unsigned long long a,
                                     unsigned long long b) {
    asm("fma.rn.f32x2 %0, %1, %2, %0;" : "+l"(c) : "l"(a), "l"(b));
}
__device__ __forceinline__ unsigned ld_acq(const unsigned* p) {
    unsigned v;
    asm volatile("ld.acquire.gpu.u32 %0, [%1];" : "=r"(v) : "l"(p));
    return v;
}
__device__ __forceinline__ void red_rel(unsigned* p, unsigned v) {
    asm volatile("red.release.gpu.add.u32 [%0], %1;" :: "l"(p), "r"(v));
}
__device__ __forceinline__ float fsig(float x) {
    return __fdividef(1.0f, 1.0f + __expf(-x));
}
__device__ __forceinline__ float ftanh(float x) {
    float xx = fminf(fmaxf(x, -15.0f), 15.0f);
    float e = __expf(2.0f * xx);
    return __fdividef(e - 1.0f, e + 1.0f);
}

// ---------------- 128x64 tile GEMM, M-paired f32x2 FFMA ----------------
// C[M,N] = A[M,K] @ B[N,K]^T (+b1 +b2) (+C if addC). N%64==0, K%16==0.
// lda/ldb are row strides of A/B; C row stride = N.
// hs >= 0: A row r = g_h[2*(hs+r)+1] + g_h[2*(hs+r)+2] (tree child-h sum).
struct GemmP {
    const float* A; const float* B; const float* b1; const float* b2;
    float* C; int M, N, K, lda, ldb, hs, addC;
};

__device__ __forceinline__ float4 loadA(const GemmP& p, int r, int koff) {
    if (r >= p.M) return make_float4(0.f, 0.f, 0.f, 0.f);
    if (p.hs >= 0) {
        int c0 = 2 * (p.hs + r) + 1;
        float4 a = *(const float4*)(g_h + (size_t)c0 * 768 + koff);
        if (c0 + 1 < 2048) {
            float4 a2 = *(const float4*)(g_h + (size_t)(c0 + 1) * 768 + koff);
            a.x += a2.x; a.y += a2.y; a.z += a2.z; a.w += a2.w;
        }
        return a;
    }
    return *(const float4*)(p.A + (size_t)r * p.lda + koff);
}

__device__ __forceinline__ void gemm_tile(const GemmP p, int tile) {
    __shared__ __align__(16) float As[16][132];
    __shared__ __align__(16) float Bs[16][68];
    const int ntx = p.N >> 6;
    const int bm = (tile / ntx) * 128;
    const int bn = (tile % ntx) * 64;
    const int tid = threadIdx.x;
    const int ty = tid >> 4;          // 0..15 -> rows ty*8..ty*8+7
    const int tx = tid & 15;          // cols tx*4
    const int ar = tid >> 2;          // 0..63 load row
    const int ac = (tid & 3) * 4;     // load col within BK

    unsigned long long acc[4][4];
#pragma unroll
    for (int i = 0; i < 4; i++)
#pragma unroll
        for (int jj = 0; jj < 4; jj++) acc[i][jj] = 0ull;

    const float* Brow = p.B + (size_t)(bn + ar) * p.ldb + ac;

    float4 a0 = loadA(p, bm + ar, ac);
    float4 a1 = loadA(p, bm + ar + 64, ac);
    float4 bv = *(const float4*)(Brow);

    for (int k0 = 0; k0 < p.K; k0 += 16) {
        __syncthreads();
        As[ac + 0][ar] = a0.x; As[ac + 1][ar] = a0.y;
        As[ac + 2][ar] = a0.z; As[ac + 3][ar] = a0.w;
        As[ac + 0][ar + 64] = a1.x; As[ac + 1][ar + 64] = a1.y;
        As[ac + 2][ar + 64] = a1.z; As[ac + 3][ar + 64] = a1.w;
        Bs[ac + 0][ar] = bv.x; Bs[ac + 1][ar] = bv.y;
        Bs[ac + 2][ar] = bv.z; Bs[ac + 3][ar] = bv.w;
        __syncthreads();
        if (k0 + 16 < p.K) {          // prefetch next K-slab under compute
            a0 = loadA(p, bm + ar, k0 + 16 + ac);
            a1 = loadA(p, bm + ar + 64, k0 + 16 + ac);
            bv = *(const float4*)(Brow + k0 + 16);
        }
#pragma unroll
        for (int kk = 0; kk < 16; kk++) {
            float4 ra0 = *(const float4*)&As[kk][ty * 8];
            float4 ra1 = *(const float4*)&As[kk][ty * 8 + 4];
            float4 rb  = *(const float4*)&Bs[kk][tx * 4];
            unsigned long long ap0 = pk2(ra0.x, ra0.y);
            unsigned long long ap1 = pk2(ra0.z, ra0.w);
            unsigned long long ap2 = pk2(ra1.x, ra1.y);
            unsigned long long ap3 = pk2(ra1.z, ra1.w);
            unsigned long long bb;
            bb = pk2(rb.x, rb.x);
            fma2(acc[0][0], ap0, bb); fma2(acc[1][0], ap1, bb);
            fma2(acc[2][0], ap2, bb); fma2(acc[3][0], ap3, bb);
            bb = pk2(rb.y, rb.y);
            fma2(acc[0][1], ap0, bb); fma2(acc[1][1], ap1, bb);
            fma2(acc[2][1], ap2, bb); fma2(acc[3][1], ap3, bb);
            bb = pk2(rb.z, rb.z);
            fma2(acc[0][2], ap0, bb); fma2(acc[1][2], ap1, bb);
            fma2(acc[2][2], ap2, bb); fma2(acc[3][2], ap3, bb);
            bb = pk2(rb.w, rb.w);
            fma2(acc[0][3], ap0, bb); fma2(acc[1][3], ap1, bb);
            fma2(acc[2][3], ap2, bb); fma2(acc[3][3], ap3, bb);
        }
    }

    const int col = bn + tx * 4;
    float4 bias = make_float4(0.f, 0.f, 0.f, 0.f);
    if (p.b1) {
        float4 bb = *(const float4*)(p.b1 + col);
        bias.x += bb.x; bias.y += bb.y; bias.z += bb.z; bias.w += bb.w;
    }
    if (p.b2) {
        float4 bb = *(const float4*)(p.b2 + col);
        bias.x += bb.x; bias.y += bb.y; bias.z += bb.z; bias.w += bb.w;
    }
#pragma unroll
    for (int m = 0; m < 4; m++) {
        float4 lo, hi;
        upk2(acc[m][0], lo.x, hi.x); upk2(acc[m][1], lo.y, hi.y);
        upk2(acc[m][2], lo.z, hi.z); upk2(acc[m][3], lo.w, hi.w);
        int row0 = bm + ty * 8 + 2 * m;
        if (row0 < p.M) {
            float* cp = p.C + (size_t)row0 * p.N + col;
            float4 o = make_float4(lo.x + bias.x, lo.y + bias.y, lo.z + bias.z, lo.w + bias.w);
            if (p.addC) {
                float4 c = *(const float4*)cp;
                o.x += c.x; o.y += c.y; o.z += c.z; o.w += c.w;
            }
            *(float4*)cp = o;
        }
        if (row0 + 1 < p.M) {
            float* cp = p.C + (size_t)(row0 + 1) * p.N + col;
            float4 o = make_float4(hi.x + bias.x, hi.y + bias.y, hi.z + bias.z, hi.w + bias.w);
            if (p.addC) {
                float4 c = *(const float4*)cp;
                o.x += c.x; o.y += c.y; o.z += c.z; o.w += c.w;
            }
            *(float4*)cp = o;
        }
    }
}

__global__ void __launch_bounds__(256) gemm_single(GemmP p) {
    gemm_tile(p, blockIdx.x);
}

__global__ void __launch_bounds__(256) gemm_dual(GemmP p1, GemmP p2, int t1) {
    int b = blockIdx.x;
    GemmP p = (b < t1) ? p1 : p2;
    int tile = (b < t1) ? b : b - t1;
    gemm_tile(p, tile);
}

// ---------------- tree LSTM elementwise kernels ----------------
__global__ void leaf_combine() {
    int idx = blockIdx.x * blockDim.x + threadIdx.x;   // 1024*768 exact
    int p = 1024 + idx / 768, jj = idx % 768;
    const float* xr = g_xiou + (size_t)p * 2304;
    float i = fsig(xr[jj]);
    float o = fsig(xr[768 + jj]);
    float u = ftanh(xr[1536 + jj]);
    float cn = i * u;
    float hn = o * ftanh(cn);
    g_c[(size_t)p * 768 + jj] = cn;
    g_h[(size_t)p * 768 + jj] = hn;
    g_cls[(size_t)p * 1536 + jj] = hn;
}

__global__ void node_combine(int s, int cnt, int cs) {
    int idx = blockIdx.x * blockDim.x + threadIdx.x;
    if (idx >= cnt * 768) return;
    int r = idx / 768, jj = idx % 768, p = s + r;
    const float* xr = g_xiou + (size_t)p * 2304;
    const float* ir = g_iou + (size_t)r * 2304;
    float i = fsig(xr[jj] + ir[jj]);
    float o = fsig(xr[768 + jj] + ir[768 + jj]);
    float u = ftanh(xr[1536 + jj] + ir[1536 + jj]);
    float xfv = g_xf[(size_t)p * 768 + jj];
    int c0 = 2 * p + 1, c1 = 2 * p + 2;
    float fc = fsig(xfv + g_fh[(size_t)(c0 - cs) * 768 + jj]) * g_c[(size_t)c0 * 768 + jj];
    if (c1 < 2048)
        fc += fsig(xfv + g_fh[(size_t)(c1 - cs) * 768 + jj]) * g_c[(size_t)c1 * 768 + jj];
    float cn = i * u + fc;
    float hn = o * ftanh(cn);
    g_c[(size_t)p * 768 + jj] = cn;
    g_h[(size_t)p * 768 + jj] = hn;
    g_cls[(size_t)p * 1536 + jj] = hn;
}

// ---------------- sequential LSTM: persistent, W_hh in registers ----------
// 96 CTAs x 256 threads. Warp w of CTA b owns output j = b*8+w.
// h is staged once per CTA through SMEM (kills the per-line L2 broadcast storm).
// No dependence on kernels launched after it: pure internal counter sync.
__global__ void __launch_bounds__(256) lstm_seq(const float* __restrict__ Whh) {
    __shared__ __align__(16) float hsm[768];
    const int tid = threadIdx.x;
    const int w = tid >> 5, l = tid & 31;
    const int j = blockIdx.x * 8 + w;
    const unsigned G = gridDim.x;

    unsigned long long wr2[4][12];
#pragma unroll
    for (int g = 0; g < 4; g++) {
        const float* base = Whh + (size_t)(g * 768 + j) * 768;
#pragma unroll
        for (int i = 0; i < 6; i++) {
            float4 v = *(const float4*)(base + 128 * i + l * 4);
            wr2[g][2 * i]     = pk2(v.x, v.y);
            wr2[g][2 * i + 1] = pk2(v.z, v.w);
        }
    }

    float cprev = 0.0f;
    for (int t = 0; t < 2048; t++) {
        // x gates are h-independent: load them while tid0 runs the step barrier
        const float* xb = g_xih + (size_t)t * 3072 + j;
        float xi = xb[0], xf_ = xb[768], xg = xb[1536], xo = xb[2304];
        if (tid == 0) {
            red_rel(&g_ctr, 1u);
            unsigned tgt = G * (unsigned)(t + 1);
            while (ld_acq(&g_ctr) < tgt) {}
        }
        __syncthreads();                        // B1: all CTAs at step t
        if (tid < 192) {
            float4 v = __ldcg((const float4*)(g_hbuf + (t & 1) * 768) + tid);
            ((float4*)hsm)[tid] = v;
        }
        __syncthreads();                        // B2: h staged in smem
        unsigned long long A0 = 0ull, A1 = 0ull, A2 = 0ull, A3 = 0ull;
#pragma unroll
        for (int i = 0; i < 6; i++) {
            float4 hv = *((const float4*)hsm + i * 32 + l);
            unsigned long long h01 = pk2(hv.x, hv.y);
            unsigned long long h23 = pk2(hv.z, hv.w);
            fma2(A0, wr2[0][2 * i], h01); fma2(A0, wr2[0][2 * i + 1], h23);
            fma2(A1, wr2[1][2 * i], h01); fma2(A1, wr2[1][2 * i + 1], h23);
            fma2(A2, wr2[2][2 * i], h01); fma2(A2, wr2[2][2 * i + 1], h23);
            fma2(A3, wr2[3][2 * i], h01); fma2(A3, wr2[3][2 * i + 1], h23);
        }
        float a0, a1, a2, a3, tlo, thi;
        upk2(A0, tlo, thi); a0 = tlo + thi;
        upk2(A1, tlo, thi); a1 = tlo + thi;
        upk2(A2, tlo, thi); a2 = tlo + thi;
        upk2(A3, tlo, thi); a3 = tlo + thi;
#pragma unroll
        for (int off = 16; off > 0; off >>= 1) {
            a0 += __shfl_xor_sync(0xffffffffu, a0, off);
            a1 += __shfl_xor_sync(0xffffffffu, a1, off);
            a2 += __shfl_xor_sync(0xffffffffu, a2, off);
            a3 += __shfl_xor_sync(0xffffffffu, a3, off);
        }
        if (l == 0) {
            float iv = fsig(a0 + xi);
            float fv = fsig(a1 + xf_);
            float gv = ftanh(a2 + xg);
            float ov = fsig(a3 + xo);
            float cn = fv * cprev + iv * gv;
            cprev = cn;
            float hn = ov * ftanh(cn);
            __stcg(&g_hbuf[((t + 1) & 1) * 768 + j], hn);
            __stcg(&g_cls[(size_t)t * 1536 + 768 + j], hn);
        }
        __syncthreads();                        // B3: stores done before next arrive
    }

    // graph-replay-safe reset: departure round so nobody still spins on g_ctr
    if (tid == 0) {
        red_rel(&g_done, 1u);
        if (blockIdx.x == 0) {
            while (ld_acq(&g_done) < G) {}
            *((volatile unsigned*)&g_ctr) = 0u;
            __threadfence();
            *((volatile unsigned*)&g_done) = 0u;
            __threadfence();
        }
    }
}

// ---------------- misc ----------------
__global__ void zero_misc() {
    int i = blockIdx.x * blockDim.x + threadIdx.x;
    if (i < 1536) g_hbuf[i] = 0.0f;
    if (i == 0) { g_ctr = 0u; g_done = 0u; }
}

__global__ void logsoftmax_col(float* __restrict__ out) {
    int o = blockIdx.x;            // 128 columns
    int tid = threadIdx.x;         // 256 threads
    __shared__ float red[256];
    float m = -1e30f;
    for (int t = tid; t < 2048; t += 256) m = fmaxf(m, g_logits[(size_t)t * 128 + o]);
    red[tid] = m; __syncthreads();
    for (int st = 128; st > 0; st >>= 1) {
        if (tid < st) red[tid] = fmaxf(red[tid], red[tid + st]);
        __syncthreads();
    }
    m = red[0]; __syncthreads();
    float s = 0.0f;
    for (int t = tid; t < 2048; t += 256) s += expf(g_logits[(size_t)t * 128 + o] - m);
    red[tid] = s; __syncthreads();
    for (int st = 128; st > 0; st >>= 1) {
        if (tid < st) red[tid] += red[tid + st];
        __syncthreads();
    }
    float lse = m + logf(red[0]);
    for (int t = tid; t < 2048; t += 256)
        out[(size_t)t * 128 + o] = g_logits[(size_t)t * 128 + o] - lse;
}

// ---------------- host ----------------
static inline int ntiles(int M, int N) { return ((M + 127) / 128) * (N / 64); }

extern "C" void kernel_launch(void* const* d_in, const int* in_sizes, int n_in,
                              void* d_out, int out_size)
{
    const float* tree_features = (const float*)d_in[0];
    const float* features      = (const float*)d_in[1];
    const float* W_iou = (const float*)d_in[2];
    const float* b_iou = (const float*)d_in[3];
    const float* U_iou = (const float*)d_in[4];
    const float* W_f   = (const float*)d_in[5];
    const float* b_f   = (const float*)d_in[6];
    const float* U_f   = (const float*)d_in[7];
    const float* W_ih  = (const float*)d_in[8];
    const float* b_ih  = (const float*)d_in[9];
    const float* W_hh  = (const float*)d_in[10];
    const float* b_hh  = (const float*)d_in[11];
    const float* W_cls = (const float*)d_in[12];
    const float* b_cls = (const float*)d_in[13];
    float* out = (float*)d_out;

    float *xiou, *xf, *xih, *h, *iou, *fh, *cls, *logits;
    cudaGetSymbolAddress((void**)&xiou,   g_xiou);
    cudaGetSymbolAddress((void**)&xf,     g_xf);
    cudaGetSymbolAddress((void**)&xih,    g_xih);
    cudaGetSymbolAddress((void**)&h,      g_h);
    cudaGetSymbolAddress((void**)&iou,    g_iou);
    cudaGetSymbolAddress((void**)&fh,     g_fh);
    cudaGetSymbolAddress((void**)&cls,    g_cls);
    cudaGetSymbolAddress((void**)&logits, g_logits);

    static cudaStream_t s2 = nullptr;
    static cudaEvent_t evFork = nullptr, evJoin = nullptr;
    if (!s2) {
        cudaStreamCreateWithFlags(&s2, cudaStreamNonBlocking);
        cudaEventCreateWithFlags(&evFork, cudaEventDisableTiming);
        cudaEventCreateWithFlags(&evJoin, cudaEventDisableTiming);
    }

    // ---- reset flags/hbuf + full xih GEMM (LSTM prerequisites, stream 0) ----
    zero_misc<<<6, 256>>>();
    GemmP pih = { features, W_ih, b_ih, b_hh, xih, 2048, 3072, 768, 768, 768, -1, 0 };
    gemm_single<<<ntiles(2048, 3072), 256>>>(pih);

    // ---- fork: seq LSTM on its own stream (no dependence on later launches) ----
    cudaEventRecord(evFork, 0);
    cudaStreamWaitEvent(s2, evFork, 0);
    lstm_seq<<<96, 256, 0, s2>>>(W_hh);
    cudaEventRecord(evJoin, s2);

    // ---- tree branch (stream 0, overlapped with LSTM) ----
    GemmP piou = { tree_features, W_iou, b_iou, nullptr, xiou, 2048, 2304, 768, 768, 768, -1, 0 };
    gemm_single<<<ntiles(2048, 2304), 256>>>(piou);
    GemmP pxf = { tree_features, W_f, b_f, nullptr, xf, 2048, 768, 768, 768, 768, -1, 0 };
    gemm_single<<<ntiles(2048, 768), 256>>>(pxf);

    leaf_combine<<<(1024 * 768) / 256, 256>>>();
    for (int lvl = 1; lvl <= 11; lvl++) {
        int s, cnt, cs, e;
        if (lvl <= 10) {
            s = 1 << (10 - lvl);
            cnt = s;
            cs = 2 * s + 1;
            int last = 4 * s; if (last > 2047) last = 2047;
            e = last - 2 * s;
        } else {
            s = 0; cnt = 1; cs = 1; e = 2;
        }
        GemmP p1 = { nullptr, U_iou, nullptr, nullptr, iou, cnt, 2304, 768, 768, 768, s, 0 };
        GemmP p2 = { h + (size_t)cs * 768, U_f, nullptr, nullptr, fh, e, 768, 768, 768, 768, -1, 0 };
        int t1 = ntiles(cnt, 2304), t2 = ntiles(e, 768);
        gemm_dual<<<t1 + t2, 256>>>(p1, p2, t1);
        node_combine<<<(cnt * 768 + 255) / 256, 256>>>(s, cnt, cs);
    }

    // ---- classifier tree-half (hidden under LSTM) ----
    GemmP pcls1 = { cls, W_cls, b_cls, nullptr, logits, 2048, 128, 768, 1536, 1536, -1, 0 };
    gemm_single<<<ntiles(2048, 128), 256>>>(pcls1);

    // ---- join + classifier lstm-half (accumulating) + log_softmax over axis 0
    cudaStreamWaitEvent(0, evJoin, 0);
    GemmP pcls2 = { cls + 768, W_cls + 768, nullptr, nullptr, logits, 2048, 128, 768, 1536, 1536, -1, 1 };
    gemm_single<<<ntiles(2048, 128), 256>>>(pcls2);
    logsoftmax_col<<<128, 256>>>(out);
}